// round 16
// baseline (speedup 1.0000x reference)
#include <cuda_runtime.h>
#include <cuda_fp16.h>
#include <cstdint>

#define BB 4
#define TT 2048
#define CC 1024
#define NH 16
#define HS 64

// ---------------- scratch (allocation-free: __device__ globals) -------------
__device__ __half g_q[BB * TT * CC];    // (B,H,T,D) fp16, pre-scaled by 0.125
__device__ __half g_k[BB * TT * CC];    // (B,H,T,D) fp16
__device__ __half g_v[BB * TT * CC];    // (B,H,D,T) fp16  (TRANSPOSED)
__device__ __half g_y[BB * TT * CC];    // (B,T,C)  fp16
__device__ __half g_xc[BB * TT * CC];   // x fp16
__device__ __half g_w4[4][CC * CC];     // W^T fp16 [n][k] : q,k,v,o

__device__ __forceinline__ void cp16(uint32_t dst, const void* src) {
    asm volatile("cp.async.cg.shared.global [%0], [%1], 16;\n" :: "r"(dst), "l"(src));
}
#define CP_COMMIT() asm volatile("cp.async.commit_group;\n" ::: "memory")
#define CP_WAIT(N)  asm volatile("cp.async.wait_group %0;\n" :: "n"(N) : "memory")

__device__ __forceinline__ void mma_f16(
    float d[4], const uint32_t a[4], uint32_t b0, uint32_t b1)
{
    asm volatile(
        "mma.sync.aligned.m16n8k16.row.col.f32.f16.f16.f32 "
        "{%0,%1,%2,%3}, {%4,%5,%6,%7}, {%8,%9}, {%0,%1,%2,%3};\n"
        : "+f"(d[0]), "+f"(d[1]), "+f"(d[2]), "+f"(d[3])
        : "r"(a[0]), "r"(a[1]), "r"(a[2]), "r"(a[3]), "r"(b0), "r"(b1));
}

__device__ __forceinline__ void ldsm_x4(
    uint32_t& r0, uint32_t& r1, uint32_t& r2, uint32_t& r3, uint32_t addr)
{
    asm volatile("ldmatrix.sync.aligned.m8n8.x4.shared.b16 {%0,%1,%2,%3}, [%4];"
                 : "=r"(r0), "=r"(r1), "=r"(r2), "=r"(r3) : "r"(addr));
}

__device__ __forceinline__ uint32_t pack_h2(float lo, float hi) {
    __half2 h = __floats2half2_rn(lo, hi);
    return *(uint32_t*)&h;
}

__device__ __forceinline__ uint32_t smem_u32(const void* p) {
    uint32_t a;
    asm("{ .reg .u64 t; cvta.to.shared.u64 t, %1; cvt.u32.u64 %0, t; }" : "=r"(a) : "l"(p));
    return a;
}

// ============================================================================
// prep: fp32 -> fp16
// ============================================================================
__global__ void round_half_kernel(const float* __restrict__ in,
                                  __half* __restrict__ out, int n4)
{
    int i = blockIdx.x * blockDim.x + threadIdx.x;
    if (i < n4) {
        float4 v = ((const float4*)in)[i];
        __half2* o = (__half2*)(out + (size_t)i * 4);
        o[0] = __floats2half2_rn(v.x, v.y);
        o[1] = __floats2half2_rn(v.z, v.w);
    }
}

// prep: all 4 weights [k][n] fp32 -> W^T [n][k] fp16 (fused, grid.z selects)
__global__ void transpose_w4_kernel(const float* __restrict__ wq,
                                    const float* __restrict__ wk,
                                    const float* __restrict__ wv,
                                    const float* __restrict__ wo)
{
    __shared__ float t[32][33];
    const int z = blockIdx.z;
    const float* in = (z == 0) ? wq : (z == 1) ? wk : (z == 2) ? wv : wo;
    __half* out = g_w4[z];
    int bx = blockIdx.x * 32, by = blockIdx.y * 32;
#pragma unroll
    for (int i = 0; i < 32; i += 8)
        t[threadIdx.y + i][threadIdx.x] = in[(size_t)(by + threadIdx.y + i) * CC + bx + threadIdx.x];
    __syncthreads();
#pragma unroll
    for (int i = 0; i < 32; i += 8)
        out[(size_t)(bx + threadIdx.y + i) * CC + by + threadIdx.x] =
            __float2half_rn(t[threadIdx.x][threadIdx.y + i]);
}

// ============================================================================
// Shared GEMM mainloop (256 threads, 8 warps 2x4, CTA tile 128x256, BK=32,
// 3-stage cp.async, ldmatrix frags). acc += A[m0:,:] @ Wt[n0:,:]^T
// ============================================================================
#define G_LD 40
#define G_NST 3
#define G_ASTAGE (128 * G_LD)
#define G_BSTAGE (256 * G_LD)
#define GEMM_SMEM ((G_NST * (G_ASTAGE + G_BSTAGE)) * 2)

__device__ __forceinline__ void gemm_mainloop(
    const __half* __restrict__ A, const __half* __restrict__ Wt,
    int m0, int n0, uint32_t as_addr, uint32_t bs_addr,
    int tid, int warp_m, int warp_n,
    int a_lrow, int a_lkof, int b_lrow, int b_lkof,
    float acc[4][8][4])
{
#define GEMM_ISSUE(BUF, K0)                                                     \
    do {                                                                        \
        uint32_t sa = as_addr + (uint32_t)(BUF) * G_ASTAGE * 2;                 \
        uint32_t sb = bs_addr + (uint32_t)(BUF) * G_BSTAGE * 2;                 \
        _Pragma("unroll")                                                       \
        for (int c = 0; c < 2; c++) {                                           \
            int id = c * 256 + tid;                                             \
            int row = id >> 2, kc = id & 3;                                     \
            cp16(sa + (row * G_LD + kc * 8) * 2,                                \
                 A  + (size_t)(m0 + row) * CC + (K0) + kc * 8);                 \
        }                                                                       \
        _Pragma("unroll")                                                       \
        for (int c = 0; c < 4; c++) {                                           \
            int id = c * 256 + tid;                                             \
            int row = id >> 2, kc = id & 3;                                     \
            cp16(sb + (row * G_LD + kc * 8) * 2,                                \
                 Wt + (size_t)(n0 + row) * CC + (K0) + kc * 8);                 \
        }                                                                       \
    } while (0)

    GEMM_ISSUE(0, 0);  CP_COMMIT();
    GEMM_ISSUE(1, 32); CP_COMMIT();
    CP_WAIT(1);
    __syncthreads();

    int buf = 0;
#pragma unroll 1
    for (int s = 0; s < 32; s++) {
        if (s + 2 < 32) { GEMM_ISSUE((s + 2) % G_NST, (s + 2) * 32); }
        CP_COMMIT();

        const uint32_t ab = as_addr + (uint32_t)buf * G_ASTAGE * 2;
        const uint32_t bb = bs_addr + (uint32_t)buf * G_BSTAGE * 2;

#pragma unroll
        for (int kk = 0; kk < 2; kk++) {
            uint32_t af[4][4];
            uint32_t bf[8][2];
#pragma unroll
            for (int i = 0; i < 4; i++) {
                int row = warp_m * 64 + i * 16 + a_lrow;
                ldsm_x4(af[i][0], af[i][1], af[i][2], af[i][3],
                        ab + (row * G_LD + kk * 16 + a_lkof) * 2);
            }
#pragma unroll
            for (int j2 = 0; j2 < 4; j2++) {
                int row = warp_n * 64 + j2 * 16 + b_lrow;
                ldsm_x4(bf[2 * j2][0], bf[2 * j2][1], bf[2 * j2 + 1][0], bf[2 * j2 + 1][1],
                        bb + (row * G_LD + kk * 16 + b_lkof) * 2);
            }
#pragma unroll
            for (int i = 0; i < 4; i++)
#pragma unroll
                for (int j = 0; j < 8; j++)
                    mma_f16(acc[i][j], af[i], bf[j][0], bf[j][1]);
        }

        CP_WAIT(1);
        __syncthreads();
        buf++; if (buf == G_NST) buf = 0;
    }
#undef GEMM_ISSUE
}

// ============================================================================
// Fused QKV GEMM: grid.z selects {Q,K,V}. CTA tile 128x256.
// z=0: Q scaled 0.125 -> (B,H,T,D); z=1: K -> (B,H,T,D); z=2: V -> (B,H,D,T).
// ============================================================================
__global__ __launch_bounds__(256, 1) void qkv_gemm_kernel(
    const __half* __restrict__ xc,
    const float* __restrict__ bq, const float* __restrict__ bk,
    const float* __restrict__ bv,
    __half* __restrict__ qp, __half* __restrict__ kp, __half* __restrict__ vp)
{
    extern __shared__ __half smh[];
    const int tid  = threadIdx.x;
    const int wid  = tid >> 5;
    const int lane = tid & 31;
    const int grp  = lane >> 2;
    const int tg   = lane & 3;

    const int z  = blockIdx.z;
    const int m0 = blockIdx.y * 128;
    const int n0 = blockIdx.x * 256;
    const int warp_m = wid >> 2;
    const int warp_n = wid & 3;

    const __half* Wt  = g_w4[z];
    const float* bias = (z == 0) ? bq : (z == 1) ? bk : bv;

    const uint32_t as_addr = smem_u32(smh);
    const uint32_t bs_addr = smem_u32(smh + G_NST * G_ASTAGE);

    const int a_lrow = (lane & 7) + ((lane >> 3) & 1) * 8;
    const int a_lkof = (lane >> 4) * 8;
    const int b_lrow = (lane & 7) + ((lane >> 4) & 1) * 8;
    const int b_lkof = ((lane >> 3) & 1) * 8;

    float acc[4][8][4];
#pragma unroll
    for (int i = 0; i < 4; i++)
#pragma unroll
        for (int j = 0; j < 8; j++)
#pragma unroll
            for (int c = 0; c < 4; c++) acc[i][j][c] = 0.0f;

    gemm_mainloop(xc, Wt, m0, n0, as_addr, bs_addr, tid, warp_m, warp_n,
                  a_lrow, a_lkof, b_lrow, b_lkof, acc);

    float2 bj[8];
#pragma unroll
    for (int j = 0; j < 8; j++)
        bj[j] = *(const float2*)(bias + n0 + warp_n * 64 + j * 8 + tg * 2);

    if (z == 2) {
        // V: warp transpose 64x64 through smem, write (B,H,D,T)
        __half* Ts = smh + wid * (64 * 72);
#pragma unroll
        for (int i = 0; i < 4; i++) {
            int r = i * 16 + grp;
#pragma unroll
            for (int j = 0; j < 8; j++) {
                int c = j * 8 + 2 * tg;
                Ts[c * 72 + r]           = __float2half_rn(acc[i][j][0] + bj[j].x);
                Ts[(c + 1) * 72 + r]     = __float2half_rn(acc[i][j][1] + bj[j].y);
                Ts[c * 72 + r + 8]       = __float2half_rn(acc[i][j][2] + bj[j].x);
                Ts[(c + 1) * 72 + r + 8] = __float2half_rn(acc[i][j][3] + bj[j].y);
            }
        }
        __syncwarp();
        const int b = m0 >> 11;
        const int h = (n0 + warp_n * 64) >> 6;
        const int t0 = (m0 & 2047) + warp_m * 64;   // batch-local token
#pragma unroll
        for (int idx = lane; idx < 512; idx += 32) {
            int c = idx >> 3, f = idx & 7;
            float4 val = *(const float4*)(Ts + c * 72 + f * 8);
            *(float4*)(vp + ((size_t)(b * NH + h) * HS + c) * TT + t0 + f * 8) = val;
        }
    } else {
        __half* out = (z == 0) ? qp : kp;
        const float scale = (z == 0) ? 0.125f : 1.0f;
#pragma unroll
        for (int i = 0; i < 4; i++) {
            int r0 = m0 + warp_m * 64 + i * 16 + grp;
#pragma unroll
            for (int j = 0; j < 8; j++) {
                int n = n0 + warp_n * 64 + j * 8 + tg * 2;
                int b = r0 >> 11, t = r0 & 2047;
                int h = n >> 6,  d = n & 63;
                size_t addr = (((size_t)(b * NH + h) * TT + t) << 6) + d;
                *(__half2*)(out + addr) =
                    __floats2half2_rn((acc[i][j][0] + bj[j].x) * scale,
                                      (acc[i][j][1] + bj[j].y) * scale);
                *(__half2*)(out + addr + 8 * 64) =
                    __floats2half2_rn((acc[i][j][2] + bj[j].x) * scale,
                                      (acc[i][j][3] + bj[j].y) * scale);
            }
        }
    }
}

// ============================================================================
// Output projection GEMM: y(half) @ Wo^T + bo -> fp32 (B,T,C). Tile 128x256.
// ============================================================================
__global__ __launch_bounds__(256, 1) void out_gemm_kernel(
    const __half* __restrict__ yh, const float* __restrict__ bo,
    float* __restrict__ out)
{
    extern __shared__ __half smh[];
    const int tid  = threadIdx.x;
    const int wid  = tid >> 5;
    const int lane = tid & 31;
    const int grp  = lane >> 2;
    const int tg   = lane & 3;

    const int m0 = blockIdx.y * 128;
    const int n0 = blockIdx.x * 256;
    const int warp_m = wid >> 2;
    const int warp_n = wid & 3;

    const uint32_t as_addr = smem_u32(smh);
    const uint32_t bs_addr = smem_u32(smh + G_NST * G_ASTAGE);

    const int a_lrow = (lane & 7) + ((lane >> 3) & 1) * 8;
    const int a_lkof = (lane >> 4) * 8;
    const int b_lrow = (lane & 7) + ((lane >> 4) & 1) * 8;
    const int b_lkof = ((lane >> 3) & 1) * 8;

    float acc[4][8][4];
#pragma unroll
    for (int i = 0; i < 4; i++)
#pragma unroll
        for (int j = 0; j < 8; j++)
#pragma unroll
            for (int c = 0; c < 4; c++) acc[i][j][c] = 0.0f;

    gemm_mainloop(yh, g_w4[3], m0, n0, as_addr, bs_addr, tid, warp_m, warp_n,
                  a_lrow, a_lkof, b_lrow, b_lkof, acc);

    float2 bj[8];
#pragma unroll
    for (int j = 0; j < 8; j++)
        bj[j] = *(const float2*)(bo + n0 + warp_n * 64 + j * 8 + tg * 2);

#pragma unroll
    for (int i = 0; i < 4; i++) {
        int r0 = m0 + warp_m * 64 + i * 16 + grp;
#pragma unroll
        for (int j = 0; j < 8; j++) {
            int n = n0 + warp_n * 64 + j * 8 + tg * 2;
            *(float2*)(out + (size_t)r0 * CC + n) =
                make_float2(acc[i][j][0] + bj[j].x, acc[i][j][1] + bj[j].y);
            *(float2*)(out + (size_t)(r0 + 8) * CC + n) =
                make_float2(acc[i][j][2] + bj[j].x, acc[i][j][3] + bj[j].y);
        }
    }
}

// ============================================================================
// Flash attention fp16 (unchanged from R14): Q tile 128, KV tiles 64, cp.async
// double-buffered, register-resident S/softmax/O, P register-repacked,
// V pre-transposed (B,H,D,T), ldmatrix frags, 2 CTAs/SM.
// ============================================================================
#define HLD 72
#define ATT_SMEM ((2 * 64 * HLD + 2 * 64 * HLD + 128 * HLD) * 2)

__global__ __launch_bounds__(256, 2) void attn_kernel(
    const __half* __restrict__ q, const __half* __restrict__ k,
    const __half* __restrict__ v, __half* __restrict__ y)
{
    extern __shared__ __half smh[];
    __half* Ks = smh;
    __half* Vs = smh + 2 * 64 * HLD;
    __half* Qs = smh + 4 * 64 * HLD;

    const int qt = (gridDim.x - 1) - blockIdx.x;
    const int h  = blockIdx.y;
    const int b  = blockIdx.z;
    const int tid  = threadIdx.x;
    const int w    = tid >> 5;
    const int lane = tid & 31;
    const int grp  = lane >> 2;
    const int tg   = lane & 3;

    const __half* qb  = q + ((size_t)(b * NH + h) * TT + (size_t)qt * 128) * HS;
    const __half* kb0 = k + (size_t)(b * NH + h) * TT * HS;
    const __half* vb0 = v + (size_t)(b * NH + h) * HS * TT;

    const uint32_t ks_addr = smem_u32(Ks);
    const uint32_t vs_addr = smem_u32(Vs);
    const uint32_t qs_addr = smem_u32(Qs);

    const int a_lrow = (lane & 7) + ((lane >> 3) & 1) * 8;
    const int a_lkof = (lane >> 4) * 8;
    const int b_lrow = (lane & 7) + ((lane >> 4) & 1) * 8;
    const int b_lkof = ((lane >> 3) & 1) * 8;

#define KV_ISSUE(KT_, BUF_)                                                     \
    do {                                                                        \
        uint32_t kbase = ks_addr + (uint32_t)(BUF_) * 64 * HLD * 2;             \
        uint32_t vbase = vs_addr + (uint32_t)(BUF_) * 64 * HLD * 2;             \
        _Pragma("unroll")                                                       \
        for (int c = 0; c < 2; c++) {                                           \
            int id = c * 256 + tid;                                             \
            int row = id >> 3, kc = id & 7;                                     \
            cp16(kbase + (row * HLD + kc * 8) * 2,                              \
                 kb0 + ((size_t)(KT_) * 64 + row) * HS + kc * 8);               \
            cp16(vbase + (row * HLD + kc * 8) * 2,                              \
                 vb0 + (size_t)row * TT + (KT_) * 64 + kc * 8);                 \
        }                                                                       \
    } while (0)

    const int nk = 2 * qt + 2;

    KV_ISSUE(0, 0);
    CP_COMMIT();
#pragma unroll
    for (int c = 0; c < 4; c++) {
        int id = c * 256 + tid;
        int row = id >> 3, kc = id & 7;
        cp16(qs_addr + (row * HLD + kc * 8) * 2, qb + (size_t)row * HS + kc * 8);
    }
    CP_COMMIT();
    CP_WAIT(0);
    __syncthreads();

    const uint32_t qw_addr = qs_addr + (uint32_t)w * 16 * HLD * 2;
    uint32_t qf[4][4];
#pragma unroll
    for (int ks = 0; ks < 4; ks++)
        ldsm_x4(qf[ks][0], qf[ks][1], qf[ks][2], qf[ks][3],
                qw_addr + (a_lrow * HLD + ks * 16 + a_lkof) * 2);

    float oacc[8][4];
#pragma unroll
    for (int j = 0; j < 8; j++)
#pragma unroll
        for (int c = 0; c < 4; c++) oacc[j][c] = 0.0f;

    float m0r = -1e30f, m1r = -1e30f, l0 = 0.0f, l1 = 0.0f;

    const int wrb  = qt * 128 + w * 16;
    const int row0 = wrb + grp;
    const int row1 = row0 + 8;

#pragma unroll 1
    for (int kt = 0; kt < nk; kt++) {
        const int buf = kt & 1;
        if (kt + 1 < nk) { KV_ISSUE(kt + 1, buf ^ 1); CP_COMMIT(); }

        const uint32_t kb = ks_addr + (uint32_t)buf * 64 * HLD * 2;
        const uint32_t vb = vs_addr + (uint32_t)buf * 64 * HLD * 2;

        if (kt * 64 <= wrb + 15) {
            float sacc[8][4];
#pragma unroll
            for (int j = 0; j < 8; j++)
#pragma unroll
                for (int c = 0; c < 4; c++) sacc[j][c] = 0.0f;

#pragma unroll
            for (int ks = 0; ks < 4; ks++) {
                uint32_t kf[8][2];
#pragma unroll
                for (int j2 = 0; j2 < 4; j2++) {
                    int row = j2 * 16 + b_lrow;
                    ldsm_x4(kf[2 * j2][0], kf[2 * j2][1], kf[2 * j2 + 1][0], kf[2 * j2 + 1][1],
                            kb + (row * HLD + ks * 16 + b_lkof) * 2);
                }
#pragma unroll
                for (int j = 0; j < 8; j++)
                    mma_f16(sacc[j], qf[ks], kf[j][0], kf[j][1]);
            }

            if (kt * 64 + 63 > wrb) {
#pragma unroll
                for (int j = 0; j < 8; j++) {
#pragma unroll
                    for (int c = 0; c < 2; c++) {
                        int col = kt * 64 + j * 8 + 2 * tg + c;
                        if (col > row0) sacc[j][c]     = -1e30f;
                        if (col > row1) sacc[j][2 + c] = -1e30f;
                    }
                }
            }

            float mx0 = -1e30f, mx1 = -1e30f;
#pragma unroll
            for (int j = 0; j < 8; j++) {
                mx0 = fmaxf(mx0, fmaxf(sacc[j][0], sacc[j][1]));
                mx1 = fmaxf(mx1, fmaxf(sacc[j][2], sacc[j][3]));
            }
            mx0 = fmaxf(mx0, __shfl_xor_sync(0xffffffffu, mx0, 1));
            mx0 = fmaxf(mx0, __shfl_xor_sync(0xffffffffu, mx0, 2));
            mx1 = fmaxf(mx1, __shfl_xor_sync(0xffffffffu, mx1, 1));
            mx1 = fmaxf(mx1, __shfl_xor_sync(0xffffffffu, mx1, 2));

            float mn0 = fmaxf(m0r, mx0), mn1 = fmaxf(m1r, mx1);
            float a0 = __expf(m0r - mn0), a1 = __expf(m1r - mn1);
            m0r = mn0; m1r = mn1;

            float s0 = 0.0f, s1 = 0.0f;
#pragma unroll
            for (int j = 0; j < 8; j++) {
                float p;
                p = __expf(sacc[j][0] - mn0); sacc[j][0] = p; s0 += p;
                p = __expf(sacc[j][1] - mn0); sacc[j][1] = p; s0 += p;
                p = __expf(sacc[j][2] - mn1); sacc[j][2] = p; s1 += p;
                p = __expf(sacc[j][3] - mn1); sacc[j][3] = p; s1 += p;
            }
            s0 += __shfl_xor_sync(0xffffffffu, s0, 1);
            s0 += __shfl_xor_sync(0xffffffffu, s0, 2);
            s1 += __shfl_xor_sync(0xffffffffu, s1, 1);
            s1 += __shfl_xor_sync(0xffffffffu, s1, 2);
            l0 = l0 * a0 + s0;
            l1 = l1 * a1 + s1;

#pragma unroll
            for (int j = 0; j < 8; j++) {
                oacc[j][0] *= a0; oacc[j][1] *= a0;
                oacc[j][2] *= a1; oacc[j][3] *= a1;
            }

#pragma unroll
            for (int ks = 0; ks < 4; ks++) {
                uint32_t pa[4];
                pa[0] = pack_h2(sacc[2 * ks][0],     sacc[2 * ks][1]);
                pa[1] = pack_h2(sacc[2 * ks][2],     sacc[2 * ks][3]);
                pa[2] = pack_h2(sacc[2 * ks + 1][0], sacc[2 * ks + 1][1]);
                pa[3] = pack_h2(sacc[2 * ks + 1][2], sacc[2 * ks + 1][3]);
                uint32_t vf[8][2];
#pragma unroll
                for (int j2 = 0; j2 < 4; j2++) {
                    int row = j2 * 16 + b_lrow;
                    ldsm_x4(vf[2 * j2][0], vf[2 * j2][1], vf[2 * j2 + 1][0], vf[2 * j2 + 1][1],
                            vb + (row * HLD + ks * 16 + b_lkof) * 2);
                }
#pragma unroll
                for (int j = 0; j < 8; j++)
                    mma_f16(oacc[j], pa, vf[j][0], vf[j][1]);
            }
        }

        if (kt + 1 < nk) CP_WAIT(0);
        __syncthreads();
    }

    float inv0 = 1.0f / l0, inv1 = 1.0f / l1;
    __half* Ow = Qs + w * 16 * HLD;
#pragma unroll
    for (int j = 0; j < 8; j++) {
        *(uint32_t*)(Ow + grp       * HLD + j * 8 + 2 * tg) =
            pack_h2(oacc[j][0] * inv0, oacc[j][1] * inv0);
        *(uint32_t*)(Ow + (grp + 8) * HLD + j * 8 + 2 * tg) =
            pack_h2(oacc[j][2] * inv1, oacc[j][3] * inv1);
    }
    __syncwarp();

    __half* yb = y + ((size_t)b * TT + qt * 128 + w * 16) * CC + h * HS;
#pragma unroll
    for (int idx = lane; idx < 128; idx += 32) {
        int r = idx >> 3, f = idx & 7;
        *(float4*)(yb + (size_t)r * CC + f * 8) = *(const float4*)(Ow + r * HLD + f * 8);
    }
#undef KV_ISSUE
}

// ============================================================================
// launch
// ============================================================================
extern "C" void kernel_launch(void* const* d_in, const int* in_sizes, int n_in,
                              void* d_out, int out_size)
{
    const float* x  = (const float*)d_in[0];
    const float* Wk = (const float*)d_in[1];
    const float* bk = (const float*)d_in[2];
    const float* Wq = (const float*)d_in[3];
    const float* bq = (const float*)d_in[4];
    const float* Wv = (const float*)d_in[5];
    const float* bv = (const float*)d_in[6];
    const float* Wo = (const float*)d_in[7];
    const float* bo = (const float*)d_in[8];
    float* out = (float*)d_out;

    __half *qp, *kp, *vp, *yp, *xc;
    cudaGetSymbolAddress((void**)&qp, g_q);
    cudaGetSymbolAddress((void**)&kp, g_k);
    cudaGetSymbolAddress((void**)&vp, g_v);
    cudaGetSymbolAddress((void**)&yp, g_y);
    cudaGetSymbolAddress((void**)&xc, g_xc);

    cudaFuncSetAttribute(qkv_gemm_kernel,
                         cudaFuncAttributeMaxDynamicSharedMemorySize, GEMM_SMEM);
    cudaFuncSetAttribute(out_gemm_kernel,
                         cudaFuncAttributeMaxDynamicSharedMemorySize, GEMM_SMEM);
    cudaFuncSetAttribute(attn_kernel,
                         cudaFuncAttributeMaxDynamicSharedMemorySize, ATT_SMEM);

    // prep: 2 launches
    int nx4 = (BB * TT * CC) / 4;
    round_half_kernel<<<nx4 / 256, 256>>>(x, xc, nx4);
    dim3 tgrid(CC / 32, CC / 32, 4), tblk(32, 8);
    transpose_w4_kernel<<<tgrid, tblk>>>(Wq, Wk, Wv, Wo);

    dim3 qkvgrid(CC / 256, (BB * TT) / 128, 3);
    qkv_gemm_kernel<<<qkvgrid, 256, GEMM_SMEM>>>(xc, bq, bk, bv, qp, kp, vp);

    dim3 agrid(TT / 128, NH, BB);
    attn_kernel<<<agrid, 256, ATT_SMEM>>>(qp, kp, vp, yp);

    dim3 ogrid(CC / 256, (BB * TT) / 128);
    out_gemm_kernel<<<ogrid, 256, GEMM_SMEM>>>(yp, bo, out);
}